// round 6
// baseline (speedup 1.0000x reference)
#include <cuda_runtime.h>
#include <cuda_bf16.h>

// Problem constants (fixed shapes)
#define NI 64      // input concentrations
#define NO 64      // output concentrations
#define NN 1024    // total N
#define NC 960     // regulated columns (N - I); global col = 64 + j
#define NCP 1024   // padded column stride (cols 960..1023 stay zero)
#define NK 896     // warmup contraction length (S rows 128..1023)
#define NWARM 25
#define GRID_P 120         // persistent warmup grid (< 148 SMs -> co-resident)
#define NBAR 25            // grid barriers per warm launch

typedef unsigned long long u64;

// ---------------- device scratch (static, allocation-free, zero-initialized) ----------------
__device__ float g_S0[NI * NCP];    // S rows 0..63, row-major [k][col], padded stride 1024
__device__ float g_u[2][NC];        // unnormalized warmup state (ping/pong)
__device__ float g_bias[NCP];       // bias_j, padded (pad = 0 -> relu contributes 0)
__device__ unsigned g_bar_count = 0;  // monotonic barrier arrivals (across replays)
__device__ unsigned g_bar_base  = 0;  // snapshot of count at launch start

// ---------------- packed f32x2 helpers ----------------
__device__ __forceinline__ u64 pack2(float x, float y) {
    u64 r; asm("mov.b64 %0, {%1, %2};" : "=l"(r) : "f"(x), "f"(y)); return r;
}
__device__ __forceinline__ void unpack2(u64 v, float& x, float& y) {
    asm("mov.b64 {%0, %1}, %2;" : "=f"(x), "=f"(y) : "l"(v));
}
__device__ __forceinline__ void ffma2(u64& acc, u64 a, u64 b) {
    asm("fma.rn.f32x2 %0, %1, %2, %0;" : "+l"(acc) : "l"(a), "l"(b));
}

__device__ __forceinline__ unsigned ld_acq(const unsigned* p) {
    unsigned v;
    asm volatile("ld.acquire.gpu.u32 %0, [%1];" : "=r"(v) : "l"(p) : "memory");
    return v;
}

// Grid-wide barrier, safe across graph replays (monotonic count + base snapshot).
__device__ __forceinline__ void grid_barrier(unsigned base, int i) {
    __syncthreads();
    if (threadIdx.x == 0) {
        __threadfence();
        atomicAdd(&g_bar_count, 1u);
        unsigned target = base + (unsigned)(i + 1) * GRID_P;
        unsigned v;
        do { v = ld_acq(&g_bar_count); } while ((int)(v - target) < 0);
    }
    __syncthreads();
}

// ---------------- fused setup + 25 warmup steps + bias (persistent, unchanged from R4) ----------
__global__ void __launch_bounds__(256, 1)
warm_kernel(const float* __restrict__ ident, const float* __restrict__ enh,
            const float* __restrict__ inh, const float* __restrict__ beta,
            const float* __restrict__ delta) {
    __shared__ float sEnhP[NK], sEnhM[NK], sInhP[NK], sInhM[NK];
    __shared__ float su[NC];
    __shared__ float spart[8];
    __shared__ unsigned s_base;

    int tid = threadIdx.x;
    int lane = tid & 31, wrp = tid >> 5;
    int col = blockIdx.x * 8 + wrp;          // 0..959

    if (tid == 0) s_base = g_bar_base;

    float b = beta[0];
    float dN = delta[0] * (1.0f / (float)NN);

    // factorized exp tables for rows 128..1023
    for (int k = tid; k < NK; k += 256) {
        float e = enh[128 + k], h = inh[128 + k];
        sEnhP[k] = __expf(-b * e);
        sEnhM[k] = __expf( b * e);
        sInhP[k] = __expf(-b * h);
        sInhM[k] = __expf( b * h);
    }
    float idj = ident[NI + col];
    float IjP = __expf( b * idj);
    float IjM = __expf(-b * idj);
    bool bpos = (b >= 0.0f);
    __syncthreads();
    unsigned base = s_base;

    // ST weights in registers: exp(-b|x-y|) = min(e^{-bx}e^{by}, e^{bx}e^{-by}) for b>=0
    float ST[28];
#pragma unroll
    for (int m = 0; m < 28; m++) {
        int k = lane + 32 * m;
        float e1 = sEnhP[k] * IjP, e2 = sEnhM[k] * IjM;
        float i1 = sInhP[k] * IjP, i2 = sInhM[k] * IjM;
        float ev = bpos ? fminf(e1, e2) : fmaxf(e1, e2);
        float iv = bpos ? fminf(i1, i2) : fmaxf(i1, i2);
        ST[m] = ev - iv;
    }

    // S0 rows (k<64) for the main GEMM (padded stride) + c0 = column sum
    float c0 = 0.0f;
#pragma unroll
    for (int q = 0; q < 2; q++) {
        int k = lane + 32 * q;
        float v = __expf(-b * fabsf(enh[k] - idj)) - __expf(-b * fabsf(inh[k] - idj));
        g_S0[k * NCP + col] = v;
        c0 += v;
    }
#pragma unroll
    for (int off = 16; off > 0; off >>= 1) c0 += __shfl_xor_sync(0xffffffffu, c0, off);

    // ---- step 0: u = const 1/N, inv = 1 ----
    {
        float acc = 0.0f;
#pragma unroll
        for (int m = 0; m < 28; m++) acc += ST[m];
#pragma unroll
        for (int off = 16; off > 0; off >>= 1) acc += __shfl_xor_sync(0xffffffffu, acc, off);
        if (lane == 0) {
            float dot = acc * (1.0f / (float)NN);
            float a = (1.0f / (float)NN) + dN * (c0 * (1.0f / (float)NN) + dot);
            g_u[1][col] = fmaxf(a, 0.0f);
        }
    }
    grid_barrier(base, 0);

    // ---- steps 1..24 + bias (t == NWARM) ----
    for (int t = 1; t <= NWARM; t++) {
        const float* __restrict__ uin = g_u[t & 1];
        float s4 = 0.0f;
        if (tid < 240) {
            float4 v = ((const float4*)uin)[tid];
            ((float4*)su)[tid] = v;
            s4 = (v.x + v.y) + (v.z + v.w);
        }
#pragma unroll
        for (int off = 16; off > 0; off >>= 1) s4 += __shfl_xor_sync(0xffffffffu, s4, off);
        if (lane == 0) spart[wrp] = s4;
        __syncthreads();
        float s = 0.0f;
#pragma unroll
        for (int q = 0; q < 8; q++) s += spart[q];   // fixed order -> identical in every block
        float inv = (s > 0.0f) ? 1.0f / s : 1.0f;

        float acc = 0.0f;
#pragma unroll
        for (int m = 0; m < 28; m++)
            acc = fmaf(ST[m], su[64 + lane + 32 * m], acc);
#pragma unroll
        for (int off = 16; off > 0; off >>= 1) acc += __shfl_xor_sync(0xffffffffu, acc, off);

        if (lane == 0) {
            float uj = su[col];
            if (t < NWARM) {
                float a = uj * inv + dN * (c0 * (1.0f / (float)NN) + inv * acc);
                g_u[(t + 1) & 1][col] = fmaxf(a, 0.0f);
            } else {
                g_bias[col] = uj * inv + dN * inv * acc;
            }
        }
        if (t < NWARM) grid_barrier(base, t);
    }

    if (blockIdx.x == 0 && tid == 0) g_bar_base = base + NBAR * GRID_P;
}

// ---------------- main batched kernel: warp-pair "team" GEMM ----------------
// Team T = warps {2T, 2T+1} handles 8 rows. Warp A (even) owns column-pairs
// m in [0,8) (includes the 64 output cols), warp B (odd) owns m in [8,16)
// (m=15 is the zero pad). Each w load now feeds 8 rows -> LDG traffic halved,
// fma pipe becomes the binding constraint.
__global__ void __launch_bounds__(256, 1)
main_kernel(const float* __restrict__ X, const float* __restrict__ delta,
            float* __restrict__ out, int B) {
    __shared__ float Xs[32 * 64];
    __shared__ float sSum[8][8];   // [warp][row-in-team] partial sums
    int tid = threadIdx.x;
    int lane = tid & 31, wid = tid >> 5;
    int T = wid >> 1;              // team 0..3
    int isB = wid & 1;
    int mbase = isB << 3;          // 0 or 8
    int row0 = blockIdx.x * 32;

    // stage X tile (32 rows x 64 cols)
    {
        const float4* Xg = (const float4*)(X + (size_t)row0 * 64);
        float4* Xs4 = (float4*)Xs;
        Xs4[tid] = Xg[tid];
        Xs4[tid + 256] = Xg[tid + 256];
    }
    __syncthreads();
    float dN = delta[0] * (1.0f / (float)NN);

    u64 acc[8][8];
#pragma unroll
    for (int r = 0; r < 8; r++)
#pragma unroll
        for (int m = 0; m < 8; m++) acc[r][m] = 0ull;

    const float* xrow = Xs + (T * 8) * 64;
    const int widx = lane + (mbase << 5);   // u64 index of this warp's first pair

#pragma unroll 2
    for (int k = 0; k < 64; k++) {
        const u64* Wk = (const u64*)(g_S0 + (size_t)k * NCP) + widx;
        u64 w[8];
#pragma unroll
        for (int m = 0; m < 8; m++) w[m] = __ldg(&Wk[m << 5]);
        u64 xp[8];
#pragma unroll
        for (int r = 0; r < 8; r++) {
            float xv = xrow[r * 64 + k];
            xp[r] = pack2(xv, xv);
        }
#pragma unroll
        for (int m = 0; m < 8; m++)
#pragma unroll
            for (int r = 0; r < 8; r++) ffma2(acc[r][m], xp[r], w[m]);
    }

    // epilogue phase 1: per-warp per-row partial sums over this warp's 512 cols
    float2 bias2[8];
#pragma unroll
    for (int m = 0; m < 8; m++)
        bias2[m] = ((const float2*)g_bias)[widx + (m << 5)];

#pragma unroll
    for (int r = 0; r < 8; r++) {
        float p = 0.0f;
#pragma unroll
        for (int m = 0; m < 8; m++) {
            float ax, ay;
            unpack2(acc[r][m], ax, ay);
            float vx = fmaxf(fmaf(dN, ax, bias2[m].x), 0.0f);
            float vy = fmaxf(fmaf(dN, ay, bias2[m].y), 0.0f);
            p += vx + vy;
        }
#pragma unroll
        for (int off = 16; off > 0; off >>= 1)
            p += __shfl_xor_sync(0xffffffffu, p, off);
        if (lane == 0) sSum[wid][r] = p;
    }
    __syncthreads();

    // epilogue phase 2: A warp combines, normalizes, stores its team's 8 rows
    if (!isB) {
#pragma unroll
        for (int r = 0; r < 8; r++) {
            float tot = sSum[wid][r] + sSum[wid + 1][r];
            float inv = (tot > 0.0f) ? 1.0f / tot : 1.0f;
            float ax, ay;
            unpack2(acc[r][0], ax, ay);   // m=0 pairs = output cols (2*lane, 2*lane+1)
            float o0 = fmaxf(fmaf(dN, ax, bias2[0].x), 0.0f) * inv;
            float o1 = fmaxf(fmaf(dN, ay, bias2[0].y), 0.0f) * inv;
            int row = row0 + T * 8 + r;
            if (row < B)
                ((float2*)out)[(size_t)row * 32 + lane] = make_float2(o0, o1);
        }
    }
}

// ---------------- launcher (2 graph nodes) ----------------
extern "C" void kernel_launch(void* const* d_in, const int* in_sizes, int n_in,
                              void* d_out, int out_size) {
    const float* X     = (const float*)d_in[0];  // (B, 64)
    const float* ident = (const float*)d_in[1];  // (1024,)
    const float* enh   = (const float*)d_in[2];  // (1024,)
    const float* inh   = (const float*)d_in[3];  // (1024,)
    const float* beta  = (const float*)d_in[4];  // (1,)
    const float* delta = (const float*)d_in[5];  // (1,)
    float* out = (float*)d_out;
    int B = in_sizes[0] / NI;

    warm_kernel<<<GRID_P, 256>>>(ident, enh, inh, beta, delta);
    main_kernel<<<(B + 31) / 32, 256>>>(X, delta, out, B);
}

// round 10
// speedup vs baseline: 1.4955x; 1.4955x over previous
#include <cuda_runtime.h>
#include <cuda_bf16.h>
#include <cstdint>

// Problem constants (fixed shapes)
#define NI 64
#define NO 64
#define NN 1024
#define NC 960     // regulated columns; global col = 64 + j
#define NCP 1024   // padded column count
#define NK 896     // warmup contraction length
#define NWARM 25
#define GRID_P 120
#define NBAR 25

typedef unsigned long long u64;

// ---------------- device scratch (static, zero-initialized) ----------------
// B' weights in mma-fragment order: region (ntile n/8, kstep k'/16) = 64 u32 (256B).
// Lane l's LDG.64 at region + l*8 yields {b0, b1} of mma.m16n8k16 B fragment.
// k' < 64: Sh rows, 64..127: Sl, 128..191: Sh.  Pad cols 960..1023 stay zero.
__device__ __nv_bfloat16 g_Bw2[128 * 12 * 128];   // 384 KB
__device__ float g_u[2][NC];
__device__ float g_bias[NCP];                     // pad entries stay 0
__device__ unsigned g_bar_count = 0;
__device__ unsigned g_bar_base  = 0;

// ---------------- small helpers ----------------
__device__ __forceinline__ unsigned ld_acq(const unsigned* p) {
    unsigned v;
    asm volatile("ld.acquire.gpu.u32 %0, [%1];" : "=r"(v) : "l"(p) : "memory");
    return v;
}
__device__ __forceinline__ void grid_barrier(unsigned base, int i) {
    __syncthreads();
    if (threadIdx.x == 0) {
        __threadfence();
        atomicAdd(&g_bar_count, 1u);
        unsigned target = base + (unsigned)(i + 1) * GRID_P;
        unsigned v;
        do { v = ld_acq(&g_bar_count); } while ((int)(v - target) < 0);
    }
    __syncthreads();
}

// mma.sync m16n8k16 row.col bf16 -> f32 (baseline PTX, valid on sm_103 target)
__device__ __forceinline__ void mma16816(float* c, const uint4& a, uint32_t b0, uint32_t b1) {
    asm("mma.sync.aligned.m16n8k16.row.col.f32.bf16.bf16.f32 "
        "{%0,%1,%2,%3}, {%4,%5,%6,%7}, {%8,%9}, {%0,%1,%2,%3};"
        : "+f"(c[0]), "+f"(c[1]), "+f"(c[2]), "+f"(c[3])
        : "r"(a.x), "r"(a.y), "r"(a.z), "r"(a.w), "r"(b0), "r"(b1));
}

// ---------------- warm kernel: setup + 25 warmup steps + bias (persistent) ----------------
__global__ void __launch_bounds__(256, 1)
warm_kernel(const float* __restrict__ ident, const float* __restrict__ enh,
            const float* __restrict__ inh, const float* __restrict__ beta,
            const float* __restrict__ delta) {
    __shared__ float sEnhP[NK], sEnhM[NK], sInhP[NK], sInhM[NK];
    __shared__ float su[NC];
    __shared__ float spart[8];
    __shared__ unsigned s_base;

    int tid = threadIdx.x;
    int lane = tid & 31, wrp = tid >> 5;
    int col = blockIdx.x * 8 + wrp;          // 0..959

    if (tid == 0) s_base = g_bar_base;

    float b = beta[0];
    float dN = delta[0] * (1.0f / (float)NN);

    for (int k = tid; k < NK; k += 256) {
        float e = enh[128 + k], h = inh[128 + k];
        sEnhP[k] = __expf(-b * e);
        sEnhM[k] = __expf( b * e);
        sInhP[k] = __expf(-b * h);
        sInhM[k] = __expf( b * h);
    }
    float idj = ident[NI + col];
    float IjP = __expf( b * idj);
    float IjM = __expf(-b * idj);
    bool bpos = (b >= 0.0f);
    __syncthreads();
    unsigned base = s_base;

    float ST[28];
#pragma unroll
    for (int m = 0; m < 28; m++) {
        int k = lane + 32 * m;
        float e1 = sEnhP[k] * IjP, e2 = sEnhM[k] * IjM;
        float i1 = sInhP[k] * IjP, i2 = sInhM[k] * IjM;
        float ev = bpos ? fminf(e1, e2) : fmaxf(e1, e2);
        float iv = bpos ? fminf(i1, i2) : fmaxf(i1, i2);
        ST[m] = ev - iv;
    }

    // S rows k<64: write bf16-split weights straight into mma-fragment layout + c0
    float c0 = 0.0f;
#pragma unroll
    for (int q = 0; q < 2; q++) {
        int k = lane + 32 * q;   // GEMM contraction index (S0 row), 0..63
        float v = __expf(-b * fabsf(enh[k] - idj)) - __expf(-b * fabsf(inh[k] - idj));
        __nv_bfloat16 h = __float2bfloat16(v);
        __nv_bfloat16 l = __float2bfloat16(v - __bfloat162float(h));
        int nt = col >> 3, nn = col & 7;
        // write (k', value) for k' in {k (Sh), 64+k (Sl), 128+k (Sh)}
#pragma unroll
        for (int w = 0; w < 3; w++) {
            int kp = k + 64 * w;
            __nv_bfloat16 val = (w == 1) ? l : h;
            int s  = kp >> 4, kk = kp & 15;
            int q2 = (kk & 7) >> 1, reg = kk >> 3, byte = kk & 1;
            int lane2 = nn * 4 + q2;
            g_Bw2[((size_t)(nt * 12 + s) << 7) + lane2 * 4 + reg * 2 + byte] = val;
        }
        c0 += v;
    }
#pragma unroll
    for (int off = 16; off > 0; off >>= 1) c0 += __shfl_xor_sync(0xffffffffu, c0, off);

    // step 0 (u = 1/N, inv = 1)
    {
        float acc = 0.0f;
#pragma unroll
        for (int m = 0; m < 28; m++) acc += ST[m];
#pragma unroll
        for (int off = 16; off > 0; off >>= 1) acc += __shfl_xor_sync(0xffffffffu, acc, off);
        if (lane == 0) {
            float dot = acc * (1.0f / (float)NN);
            float a = (1.0f / (float)NN) + dN * (c0 * (1.0f / (float)NN) + dot);
            g_u[1][col] = fmaxf(a, 0.0f);
        }
    }
    grid_barrier(base, 0);

    for (int t = 1; t <= NWARM; t++) {
        const float* __restrict__ uin = g_u[t & 1];
        float s4 = 0.0f;
        if (tid < 240) {
            float4 v = ((const float4*)uin)[tid];
            ((float4*)su)[tid] = v;
            s4 = (v.x + v.y) + (v.z + v.w);
        }
#pragma unroll
        for (int off = 16; off > 0; off >>= 1) s4 += __shfl_xor_sync(0xffffffffu, s4, off);
        if (lane == 0) spart[wrp] = s4;
        __syncthreads();
        float s = 0.0f;
#pragma unroll
        for (int q = 0; q < 8; q++) s += spart[q];
        float inv = (s > 0.0f) ? 1.0f / s : 1.0f;

        float acc = 0.0f;
#pragma unroll
        for (int m = 0; m < 28; m++)
            acc = fmaf(ST[m], su[64 + lane + 32 * m], acc);
#pragma unroll
        for (int off = 16; off > 0; off >>= 1) acc += __shfl_xor_sync(0xffffffffu, acc, off);

        if (lane == 0) {
            float uj = su[col];
            if (t < NWARM) {
                float a = uj * inv + dN * (c0 * (1.0f / (float)NN) + inv * acc);
                g_u[(t + 1) & 1][col] = fmaxf(a, 0.0f);
            } else {
                g_bias[col] = uj * inv + dN * inv * acc;
            }
        }
        if (t < NWARM) grid_barrier(base, t);
    }

    if (blockIdx.x == 0 && tid == 0) g_bar_base = base + NBAR * GRID_P;
}

// ---------------- main batched kernel: warp mma.sync bf16 split-K GEMM ----------------
// CTA: 64 rows x 1024 cols (4 chunks of 256). 8 warps = 2 m-groups x 4 n-groups;
// warp tile = 32 rows x 64 cols per chunk (2 m-tiles x 8 n-tiles of m16n8k16).
// A' [64 rows x 192 k] bf16 staged in smem in fragment order; B' from global in
// fragment order (one LDG.64 per lane per fragment).
__global__ void __launch_bounds__(256, 2)
main3_kernel(const float* __restrict__ X, const float* __restrict__ delta,
             float* __restrict__ out, int B) {
    __shared__ uint32_t Asm[4 * 12 * 128];   // 24 KB: (mtile,kstep) regions of 512B
    __shared__ float bias_s[NCP];            // 4 KB
    __shared__ float Os[64 * 64];            // 16 KB: relu'd output cols 0..63
    __shared__ float sums[64][4];            // per-row per-ngroup partial sums
    __shared__ float inv_s[64];

    int tid = threadIdx.x;
    int lane = tid & 31, wid = tid >> 5;
    int mg = wid >> 2;        // 0..1  (rows mg*32 .. +31)
    int ng = wid & 3;         // 0..3  (cols ng*64 within each 256-chunk)
    int row0 = blockIdx.x * 64;

    for (int i = tid; i < NCP; i += 256) bias_s[i] = g_bias[i];

    // ---- build A' fragments: 64 rows x 96 k-pairs -> 6144 u32 slots ----
    // slot(r, p): k'=2p; value = pack(bf16 pair). p<32: Xh(2p,2p+1); 32..63: Xh(2p-64);
    // 64..95: Xl(2p-128). Slot addr: region (mt = r>>4, s = p>>3), lane=(r&7)*4+(p&3),
    // reg = ((r>>3)&1) | (((p>>2)&1)<<1).
#pragma unroll
    for (int it = 0; it < 24; it++) {
        int idx = tid + it * 256;       // 0..6143
        int r = idx / 96, p = idx - r * 96;
        int xc = (2 * p) & 63;
        float x0 = 0.0f, x1 = 0.0f;
        if (row0 + r < B) {
            const float* xp = X + (size_t)(row0 + r) * 64 + xc;
            x0 = xp[0]; x1 = xp[1];
        }
        __nv_bfloat16 h0 = __float2bfloat16(x0);
        __nv_bfloat16 h1 = __float2bfloat16(x1);
        __nv_bfloat16 v0, v1;
        if (p < 64) { v0 = h0; v1 = h1; }
        else {
            v0 = __float2bfloat16(x0 - __bfloat162float(h0));
            v1 = __float2bfloat16(x1 - __bfloat162float(h1));
        }
        uint32_t pk = (uint32_t)__bfloat16_as_ushort(v0)
                    | ((uint32_t)__bfloat16_as_ushort(v1) << 16);
        int mt = r >> 4, s = p >> 3;
        int ln = ((r & 7) << 2) + (p & 3);
        int rg = ((r >> 3) & 1) | (((p >> 2) & 1) << 1);
        Asm[((mt * 12 + s) << 7) + (ln << 2) + rg] = pk;
    }
    __syncthreads();

    float dN = delta[0] * (1.0f / (float)NN);
    const u64* __restrict__ Bg = (const u64*)g_Bw2;

    float ps[4] = {0.0f, 0.0f, 0.0f, 0.0f};   // row-offset partials {0,8,16,24}+lane/4

    for (int c = 0; c < 4; c++) {
        float C[2][8][4];
#pragma unroll
        for (int i = 0; i < 2; i++)
#pragma unroll
            for (int t = 0; t < 8; t++)
#pragma unroll
                for (int j = 0; j < 4; j++) C[i][t][j] = 0.0f;

        int ntb = c * 32 + ng * 8;
#pragma unroll 2
        for (int s = 0; s < 12; s++) {
            uint4 a[2];
#pragma unroll
            for (int i = 0; i < 2; i++)
                a[i] = *(const uint4*)&Asm[(((mg * 2 + i) * 12 + s) << 7) + (lane << 2)];
#pragma unroll
            for (int t = 0; t < 8; t++) {
                u64 bv = __ldg(&Bg[(((ntb + t) * 12 + s) << 5) + lane]);
                uint32_t b0 = (uint32_t)bv, b1 = (uint32_t)(bv >> 32);
                mma16816(C[0][t], a[0], b0, b1);
                mma16816(C[1][t], a[1], b0, b1);
            }
        }

        // epilogue: bias + relu, accumulate deterministic row partials, save out cols
#pragma unroll
        for (int i = 0; i < 2; i++)
#pragma unroll
            for (int t = 0; t < 8; t++) {
                int colg = (c << 8) + (ng << 6) + (t << 3) + ((lane & 3) << 1);
                float b0f = bias_s[colg], b1f = bias_s[colg + 1];
                float v00 = fmaxf(fmaf(dN, C[i][t][0], b0f), 0.0f);
                float v01 = fmaxf(fmaf(dN, C[i][t][1], b1f), 0.0f);
                float v10 = fmaxf(fmaf(dN, C[i][t][2], b0f), 0.0f);
                float v11 = fmaxf(fmaf(dN, C[i][t][3], b1f), 0.0f);
                ps[i * 2 + 0] += v00 + v01;
                ps[i * 2 + 1] += v10 + v11;
                if (c == 0 && ng == 0) {
                    int r0 = (mg << 5) + (i << 4) + (lane >> 2);
                    int cl = (t << 3) + ((lane & 3) << 1);
                    Os[r0 * 64 + cl] = v00;       Os[r0 * 64 + cl + 1] = v01;
                    Os[(r0 + 8) * 64 + cl] = v10; Os[(r0 + 8) * 64 + cl + 1] = v11;
                }
            }
    }

    // reduce partials over the 4 lanes sharing a row (lane&3), fixed order
#pragma unroll
    for (int j = 0; j < 4; j++) {
        ps[j] += __shfl_xor_sync(0xffffffffu, ps[j], 1);
        ps[j] += __shfl_xor_sync(0xffffffffu, ps[j], 2);
    }
    if ((lane & 3) == 0) {
        int rr = lane >> 2;
#pragma unroll
        for (int j = 0; j < 4; j++) {
            int row = (mg << 5) + ((j >> 1) << 4) + ((j & 1) << 3) + rr;
            sums[row][ng] = ps[j];
        }
    }
    __syncthreads();
    if (tid < 64) {
        float s = ((sums[tid][0] + sums[tid][1]) + (sums[tid][2] + sums[tid][3]));
        inv_s[tid] = (s > 0.0f) ? 1.0f / s : 1.0f;
    }
    __syncthreads();

    for (int i = tid; i < 64 * 64; i += 256) {
        int r = i >> 6, cc = i & 63;
        int row = row0 + r;
        if (row < B)
            out[(size_t)row * 64 + cc] = Os[i] * inv_s[r];
    }
}

// ---------------- launcher (2 graph nodes) ----------------
extern "C" void kernel_launch(void* const* d_in, const int* in_sizes, int n_in,
                              void* d_out, int out_size) {
    const float* X     = (const float*)d_in[0];
    const float* ident = (const float*)d_in[1];
    const float* enh   = (const float*)d_in[2];
    const float* inh   = (const float*)d_in[3];
    const float* beta  = (const float*)d_in[4];
    const float* delta = (const float*)d_in[5];
    float* out = (float*)d_out;
    int B = in_sizes[0] / NI;

    warm_kernel<<<GRID_P, 256>>>(ident, enh, inh, beta, delta);
    main3_kernel<<<(B + 63) / 64, 256>>>(X, delta, out, B);
}

// round 11
// speedup vs baseline: 1.8782x; 1.2558x over previous
#include <cuda_runtime.h>
#include <cuda_bf16.h>
#include <cstdint>

// Problem constants (fixed shapes)
#define NI 64
#define NO 64
#define NN 1024
#define NC 960     // regulated columns; global col = 64 + j
#define NCP 1024   // padded column count
#define NK 896     // warmup contraction length (rows 128..1023)
#define NWARM 25

typedef unsigned long long u64;

// ---------------- device scratch (static, zero-initialized) ----------------
// B' weights in mma-fragment order (validated in R9). Pad cols stay zero.
__device__ __nv_bfloat16 g_Bw2[128 * 12 * 128];   // 384 KB
__device__ float g_bias[NCP];                      // pad entries stay 0
// warm precompute tables (written by setup kernel)
__device__ float g_wE1[NK], g_wE2r[NK], g_wI1[NK], g_wI2r[NK];
__device__ unsigned short g_pE1[NK], g_pE2r[NK], g_pI1[NK], g_pI2r[NK];
__device__ unsigned short g_cE[NC], g_cI[NC];
__device__ float g_fM[NC], g_fP[NC], g_c0v[NC];
__device__ unsigned g_done;    // reset to 0 by setup kernel every launch (graph edge orders)

// ---------------- helpers ----------------
__device__ __forceinline__ unsigned ld_acq(const unsigned* p) {
    unsigned v;
    asm volatile("ld.acquire.gpu.u32 %0, [%1];" : "=r"(v) : "l"(p) : "memory");
    return v;
}
__device__ __forceinline__ void mma16816(float* c, const uint4& a, uint32_t b0, uint32_t b1) {
    asm("mma.sync.aligned.m16n8k16.row.col.f32.bf16.bf16.f32 "
        "{%0,%1,%2,%3}, {%4,%5,%6,%7}, {%8,%9}, {%0,%1,%2,%3};"
        : "+f"(c[0]), "+f"(c[1]), "+f"(c[2]), "+f"(c[3])
        : "r"(a.x), "r"(a.y), "r"(a.z), "r"(a.w), "r"(b0), "r"(b1));
}

// ---------------- setup kernel: B' frags + sort ranks + cut tables + factors ----------------
__global__ void __launch_bounds__(256)
setup_kernel(const float* __restrict__ ident, const float* __restrict__ enh,
             const float* __restrict__ inh, const float* __restrict__ beta) {
    int bid = blockIdx.x, tid = threadIdx.x;
    int lane = tid & 31, wrp = tid >> 5;
    float b = beta[0];
    if (bid == 0 && tid == 0) g_done = 0;   // replay-safe flag reset

    if (bid < 120) {
        // ---- B' fragments (verbatim R9 layout) + c0 + per-col exp factors ----
        int col = bid * 8 + wrp;
        float idj = ident[NI + col];
        float c0 = 0.0f;
#pragma unroll
        for (int q = 0; q < 2; q++) {
            int k = lane + 32 * q;
            float v = __expf(-b * fabsf(enh[k] - idj)) - __expf(-b * fabsf(inh[k] - idj));
            __nv_bfloat16 h = __float2bfloat16(v);
            __nv_bfloat16 l = __float2bfloat16(v - __bfloat162float(h));
            int nt = col >> 3, nn = col & 7;
#pragma unroll
            for (int w = 0; w < 3; w++) {
                int kp = k + 64 * w;
                __nv_bfloat16 val = (w == 1) ? l : h;
                int s = kp >> 4, kk = kp & 15;
                int q2 = (kk & 7) >> 1, reg = kk >> 3, byt = kk & 1;
                g_Bw2[((size_t)(nt * 12 + s) << 7) + (nn * 4 + q2) * 4 + reg * 2 + byt] = val;
            }
            c0 += v;
        }
#pragma unroll
        for (int off = 16; off; off >>= 1) c0 += __shfl_xor_sync(~0u, c0, off);
        if (lane == 0) {
            g_c0v[col] = c0;
            g_fM[col] = __expf(-b * idj);
            g_fP[col] = __expf( b * idj);
        }
    } else if (bid < 232) {
        // ---- ranks + scatter for enh (120..175) / inh (176..231), 16 elems/block ----
        bool isE = bid < 176;
        const float* src = (isE ? enh : inh) + 128;
        __shared__ float E[NK];
        for (int i = tid; i < NK; i += 256) E[i] = src[i];
        __syncthreads();
        int el = (isE ? bid - 120 : bid - 176) * 16 + (tid >> 4);
        int sub = tid & 15;
        float ei = E[el];
        int cnt = 0;
        for (int m = sub; m < NK; m += 16) {
            float em = E[m];
            cnt += (em < ei) || (em == ei && m < el);   // lexicographic -> permutation
        }
        cnt += __shfl_xor_sync(~0u, cnt, 1);
        cnt += __shfl_xor_sync(~0u, cnt, 2);
        cnt += __shfl_xor_sync(~0u, cnt, 4);
        cnt += __shfl_xor_sync(~0u, cnt, 8);
        if (sub == 0) {
            int r = cnt;
            unsigned short uidx = (unsigned short)(64 + el);   // u index = 64 + k
            float wp = __expf( b * ei), wm = __expf(-b * ei);
            if (isE) { g_wE1[r] = wp; g_pE1[r] = uidx; g_wE2r[895 - r] = wm; g_pE2r[895 - r] = uidx; }
            else     { g_wI1[r] = wp; g_pI1[r] = uidx; g_wI2r[895 - r] = wm; g_pI2r[895 - r] = uidx; }
        }
    } else {
        // ---- cut counts c_j = #{e_k <= t_j}, 8 j per block (232..351) ----
        __shared__ float E[NK], Iv[NK];
        for (int i = tid; i < NK; i += 256) { E[i] = enh[128 + i]; Iv[i] = inh[128 + i]; }
        __syncthreads();
        int j = (bid - 232) * 8 + (tid >> 5);
        float t = ident[NI + j];
        int cE = 0, cI = 0;
        for (int m = lane; m < NK; m += 32) {
            cE += (E[m] <= t);
            cI += (Iv[m] <= t);
        }
#pragma unroll
        for (int off = 16; off; off >>= 1) {
            cE += __shfl_xor_sync(~0u, cE, off);
            cI += __shfl_xor_sync(~0u, cI, off);
        }
        if (lane == 0) { g_cE[j] = (unsigned short)cE; g_cI[j] = (unsigned short)cI; }
    }
}

// ---------------- fused kernel: block0 = warmup (scan), blocks 1.. = GEMM tiles --------------
struct WarmS {
    float su[2][NC];
    float P1E[897], T2E[897], P1I[897], T2I[897];
    float wE1[NK], wE2r[NK], wI1[NK], wI2r[NK];
    float fM[NC], fP[NC], c0[NC];
    float4 warpTot[8];
    float sred[8];
    float s_inv;
    unsigned short pE1[NK], pE2r[NK], pI1[NK], pI2r[NK];
    unsigned short cE[NC], cI[NC];
};
struct GemmS {
    uint32_t Asm[4 * 12 * 128];   // 24576 B
    float bias[NCP];              // 4096
    float Os[64 * 64];            // 16384
    float stash[64][256];         // 65536 (thread-private raw C of chunk 0)
    float sums[64][4];            // 1024
    float inv_s[64];              // 256
};                                // = 111,872 B total

__global__ void __launch_bounds__(256, 2)
fused_kernel(const float* __restrict__ X, const float* __restrict__ delta,
             float* __restrict__ out, int B) {
    extern __shared__ __align__(16) char smem[];
    int tid = threadIdx.x, lane = tid & 31, wid = tid >> 5;
    float dN = delta[0] * (1.0f / (float)NN);

    if (blockIdx.x == 0) {
        // ================= WARMUP (single block, prefix-sum factorization) =================
        WarmS* W = (WarmS*)smem;
        for (int i = tid; i < NK; i += 256) {
            W->wE1[i] = g_wE1[i]; W->wE2r[i] = g_wE2r[i];
            W->wI1[i] = g_wI1[i]; W->wI2r[i] = g_wI2r[i];
            W->pE1[i] = g_pE1[i]; W->pE2r[i] = g_pE2r[i];
            W->pI1[i] = g_pI1[i]; W->pI2r[i] = g_pI2r[i];
        }
        for (int i = tid; i < NC; i += 256) {
            W->cE[i] = g_cE[i]; W->cI[i] = g_cI[i];
            W->fM[i] = g_fM[i]; W->fP[i] = g_fP[i]; W->c0[i] = g_c0v[i];
            W->su[0][i] = 1.0f / (float)NN;
        }
        if (tid == 0) { W->P1E[0] = 0.f; W->T2E[0] = 0.f; W->P1I[0] = 0.f; W->T2I[0] = 0.f; }
        __syncthreads();

        float inv = 1.0f;
        for (int t = 0; t <= NWARM; t++) {
            float* su = W->su[t & 1];
            float* un = W->su[(t + 1) & 1];
            int i0 = tid * 4;
            float4 pre[4]; float4 excl;
            // ---- phase A: weighted gathers + float4 block scan over 896 (warps 0..6) ----
            if (wid < 7) {
                float4 run = {0.f, 0.f, 0.f, 0.f};
#pragma unroll
                for (int q = 0; q < 4; q++) {
                    int i = i0 + q;
                    run.x += W->wE1[i]  * su[W->pE1[i]];
                    run.y += W->wE2r[i] * su[W->pE2r[i]];
                    run.z += W->wI1[i]  * su[W->pI1[i]];
                    run.w += W->wI2r[i] * su[W->pI2r[i]];
                    pre[q] = run;
                }
                float4 tot = run, w4 = run;
#pragma unroll
                for (int off = 1; off < 32; off <<= 1) {
                    float ux = __shfl_up_sync(~0u, w4.x, off);
                    float uy = __shfl_up_sync(~0u, w4.y, off);
                    float uz = __shfl_up_sync(~0u, w4.z, off);
                    float uw = __shfl_up_sync(~0u, w4.w, off);
                    if (lane >= off) { w4.x += ux; w4.y += uy; w4.z += uz; w4.w += uw; }
                }
                excl.x = w4.x - tot.x; excl.y = w4.y - tot.y;
                excl.z = w4.z - tot.z; excl.w = w4.w - tot.w;
                if (lane == 31) W->warpTot[wid] = w4;
            }
            __syncthreads();
            if (wid < 7) {
                float4 base = excl;
                for (int ww = 0; ww < wid; ww++) {
                    float4 wt = W->warpTot[ww];
                    base.x += wt.x; base.y += wt.y; base.z += wt.z; base.w += wt.w;
                }
#pragma unroll
                for (int q = 0; q < 4; q++) {
                    int i = i0 + q;
                    W->P1E[i + 1] = base.x + pre[q].x;
                    W->T2E[i + 1] = base.y + pre[q].y;
                    W->P1I[i + 1] = base.z + pre[q].z;
                    W->T2I[i + 1] = base.w + pre[q].w;
                }
            }
            __syncthreads();
            // ---- phase B: per-column combine ----
            float msum = 0.f;
#pragma unroll
            for (int r = 0; r < 4; r++) {
                int j = tid + 256 * r;
                if (j < NC) {
                    int c1 = W->cE[j], c2 = W->cI[j];
                    float dot = W->fM[j] * (W->P1E[c1] - W->P1I[c2])
                              + W->fP[j] * (W->T2E[896 - c1] - W->T2I[896 - c2]);
                    float uj = su[j];
                    if (t < NWARM) {
                        float a = fmaxf(uj * inv + dN * (W->c0[j] * (1.0f / (float)NN) + inv * dot), 0.0f);
                        un[j] = a; msum += a;
                    } else {
                        g_bias[j] = uj * inv + dN * inv * dot;
                    }
                }
            }
            // ---- phase C: deterministic s reduction ----
            if (t < NWARM) {
#pragma unroll
                for (int off = 16; off; off >>= 1) msum += __shfl_xor_sync(~0u, msum, off);
                if (lane == 0) W->sred[wid] = msum;
                __syncthreads();
                if (tid == 0) {
                    float s = 0.f;
#pragma unroll
                    for (int q = 0; q < 8; q++) s += W->sred[q];
                    W->s_inv = (s > 0.0f) ? 1.0f / s : 1.0f;
                }
                __syncthreads();
                inv = W->s_inv;
            }
        }
        __threadfence();
        __syncthreads();
        if (tid == 0)
            asm volatile("st.release.gpu.global.u32 [%0], %1;" :: "l"(&g_done), "r"(1u) : "memory");
    } else {
        // ================= GEMM tile (R9 main3, chunk0 stashed, bias waited late) ==========
        GemmS* G = (GemmS*)smem;
        int mg = wid >> 2, ng = wid & 3;
        int row0 = (int)(blockIdx.x - 1) * 64;

        // A' fragments (verbatim R9)
#pragma unroll
        for (int it = 0; it < 24; it++) {
            int idx = tid + it * 256;
            int r = idx / 96, p = idx - r * 96;
            int xc = (2 * p) & 63;
            float x0 = 0.0f, x1 = 0.0f;
            if (row0 + r < B) {
                const float* xp = X + (size_t)(row0 + r) * 64 + xc;
                x0 = xp[0]; x1 = xp[1];
            }
            __nv_bfloat16 h0 = __float2bfloat16(x0);
            __nv_bfloat16 h1 = __float2bfloat16(x1);
            __nv_bfloat16 v0, v1;
            if (p < 64) { v0 = h0; v1 = h1; }
            else {
                v0 = __float2bfloat16(x0 - __bfloat162float(h0));
                v1 = __float2bfloat16(x1 - __bfloat162float(h1));
            }
            uint32_t pk = (uint32_t)__bfloat16_as_ushort(v0)
                        | ((uint32_t)__bfloat16_as_ushort(v1) << 16);
            int mt = r >> 4, s = p >> 3;
            int ln = ((r & 7) << 2) + (p & 3);
            int rg = ((r >> 3) & 1) | (((p >> 2) & 1) << 1);
            G->Asm[((mt * 12 + s) << 7) + (ln << 2) + rg] = pk;
        }
        __syncthreads();

        const u64* __restrict__ Bg = (const u64*)g_Bw2;
        float ps[4] = {0.f, 0.f, 0.f, 0.f};

        for (int ci = 0; ci < 4; ci++) {
            int c = ci;
            float C[2][8][4];
#pragma unroll
            for (int i = 0; i < 2; i++)
#pragma unroll
                for (int t = 0; t < 8; t++)
#pragma unroll
                    for (int j = 0; j < 4; j++) C[i][t][j] = 0.f;

            int ntb = c * 32 + ng * 8;
#pragma unroll 2
            for (int s = 0; s < 12; s++) {
                uint4 a[2];
#pragma unroll
                for (int i = 0; i < 2; i++)
                    a[i] = *(const uint4*)&G->Asm[(((mg * 2 + i) * 12 + s) << 7) + (lane << 2)];
#pragma unroll
                for (int t = 0; t < 8; t++) {
                    u64 bv = __ldg(&Bg[(((ntb + t) * 12 + s) << 5) + lane]);
                    uint32_t b0 = (uint32_t)bv, b1 = (uint32_t)(bv >> 32);
                    mma16816(C[0][t], a[0], b0, b1);
                    mma16816(C[1][t], a[1], b0, b1);
                }
            }

            if (ci == 0) {
                // stash raw chunk-0 accumulators (thread-private, no sync needed)
#pragma unroll
                for (int i = 0; i < 2; i++)
#pragma unroll
                    for (int t = 0; t < 8; t++) {
                        int base = (i * 8 + t) * 4;
                        G->stash[base + 0][tid] = C[i][t][0];
                        G->stash[base + 1][tid] = C[i][t][1];
                        G->stash[base + 2][tid] = C[i][t][2];
                        G->stash[base + 3][tid] = C[i][t][3];
                    }
                continue;
            }
            if (ci == 1) {
                // first epilogue: wait for warmup's bias publication
                if (tid == 0) { while (ld_acq(&g_done) == 0) {} }
                __syncthreads();
                for (int i = tid; i < NCP; i += 256) G->bias[i] = g_bias[i];
                __syncthreads();
            }
            // epilogue for chunk c (c = 1..3; no output cols here)
#pragma unroll
            for (int i = 0; i < 2; i++)
#pragma unroll
                for (int t = 0; t < 8; t++) {
                    int colg = (c << 8) + (ng << 6) + (t << 3) + ((lane & 3) << 1);
                    float b0f = G->bias[colg], b1f = G->bias[colg + 1];
                    float v00 = fmaxf(fmaf(dN, C[i][t][0], b0f), 0.0f);
                    float v01 = fmaxf(fmaf(dN, C[i][t][1], b1f), 0.0f);
                    float v10 = fmaxf(fmaf(dN, C[i][t][2], b0f), 0.0f);
                    float v11 = fmaxf(fmaf(dN, C[i][t][3], b1f), 0.0f);
                    ps[i * 2 + 0] += v00 + v01;
                    ps[i * 2 + 1] += v10 + v11;
                }
        }

        // epilogue for chunk 0 (from stash; includes output cols when ng==0)
#pragma unroll
        for (int i = 0; i < 2; i++)
#pragma unroll
            for (int t = 0; t < 8; t++) {
                int base = (i * 8 + t) * 4;
                float c0v = G->stash[base + 0][tid];
                float c1v = G->stash[base + 1][tid];
                float c2v = G->stash[base + 2][tid];
                float c3v = G->stash[base + 3][tid];
                int colg = (ng << 6) + (t << 3) + ((lane & 3) << 1);
                float b0f = G->bias[colg], b1f = G->bias[colg + 1];
                float v00 = fmaxf(fmaf(dN, c0v, b0f), 0.0f);
                float v01 = fmaxf(fmaf(dN, c1v, b1f), 0.0f);
                float v10 = fmaxf(fmaf(dN, c2v, b0f), 0.0f);
                float v11 = fmaxf(fmaf(dN, c3v, b1f), 0.0f);
                ps[i * 2 + 0] += v00 + v01;
                ps[i * 2 + 1] += v10 + v11;
                if (ng == 0) {
                    int r0 = (mg << 5) + (i << 4) + (lane >> 2);
                    int cl = (t << 3) + ((lane & 3) << 1);
                    G->Os[r0 * 64 + cl] = v00;         G->Os[r0 * 64 + cl + 1] = v01;
                    G->Os[(r0 + 8) * 64 + cl] = v10;   G->Os[(r0 + 8) * 64 + cl + 1] = v11;
                }
            }

        // deterministic row sums + normalize + store (verbatim R9)
#pragma unroll
        for (int j = 0; j < 4; j++) {
            ps[j] += __shfl_xor_sync(~0u, ps[j], 1);
            ps[j] += __shfl_xor_sync(~0u, ps[j], 2);
        }
        if ((lane & 3) == 0) {
            int rr = lane >> 2;
#pragma unroll
            for (int j = 0; j < 4; j++) {
                int row = (mg << 5) + ((j >> 1) << 4) + ((j & 1) << 3) + rr;
                G->sums[row][ng] = ps[j];
            }
        }
        __syncthreads();
        if (tid < 64) {
            float s = ((G->sums[tid][0] + G->sums[tid][1]) + (G->sums[tid][2] + G->sums[tid][3]));
            G->inv_s[tid] = (s > 0.0f) ? 1.0f / s : 1.0f;
        }
        __syncthreads();
        for (int i = tid; i < 64 * 64; i += 256) {
            int r = i >> 6, cc = i & 63;
            int row = row0 + r;
            if (row < B)
                out[(size_t)row * 64 + cc] = G->Os[i] * G->inv_s[r];
        }
    }
}

// ---------------- launcher (2 graph nodes) ----------------
extern "C" void kernel_launch(void* const* d_in, const int* in_sizes, int n_in,
                              void* d_out, int out_size) {
    const float* X     = (const float*)d_in[0];
    const float* ident = (const float*)d_in[1];
    const float* enh   = (const float*)d_in[2];
    const float* inh   = (const float*)d_in[3];
    const float* beta  = (const float*)d_in[4];
    const float* delta = (const float*)d_in[5];
    float* out = (float*)d_out;
    int B = in_sizes[0] / NI;

    cudaFuncSetAttribute(fused_kernel, cudaFuncAttributeMaxDynamicSharedMemorySize,
                         (int)sizeof(GemmS));

    setup_kernel<<<352, 256>>>(ident, enh, inh, beta);
    int tiles = (B + 63) / 64;
    fused_kernel<<<1 + tiles, 256, sizeof(GemmS)>>>(X, delta, out, B);
}